// round 1
// baseline (speedup 1.0000x reference)
#include <cuda_runtime.h>
#include <cstdint>

// ---------------- problem constants ----------------
constexpr int Dm    = 768;     // d_model
constexpr int NE    = 4;       // experts
constexpr int Rr    = 32;      // rank
constexpr int Bb    = 4;       // batch
constexpr int Tt    = 512;     // seq len
constexpr int NTOK  = Bb * Tt; // 2048
constexpr int NV    = 50257;   // vocab

// ---------------- scratch (no allocations allowed) ----------------
__device__ float g_x[NTOK * Dm];        // embedded tokens
__device__ float g_u[NTOK * NE * Rr];   // x @ W_in  (all experts)
__device__ float g_cand[NTOK * Rr];     // winner's cand per token
__device__ float g_h[NTOK * Dm];        // layernormed residual stream
__device__ int   g_win[NTOK];           // winner expert per token

// =================================================================
// Kernel A: embedding gather + routing argmax + u = x @ W_in
// one block per token, 256 threads
// =================================================================
__global__ void embed_route_kernel(const int* __restrict__ idx,
                                   const float* __restrict__ W_emb,
                                   const float* __restrict__ G,
                                   const float* __restrict__ W_in) {
    __shared__ float xs[Dm];
    __shared__ float sred[NE][256];
    __shared__ float upart[256];

    const int tok = blockIdx.x;
    const int tid = threadIdx.x;
    const int id  = idx[tok];

    float sc[NE] = {0.f, 0.f, 0.f, 0.f};
    for (int d = tid; d < Dm; d += 256) {
        float v = W_emb[(size_t)id * Dm + d];
        xs[d] = v;
        g_x[tok * Dm + d] = v;
#pragma unroll
        for (int e = 0; e < NE; e++) sc[e] += v * G[e * Dm + d];
    }
#pragma unroll
    for (int e = 0; e < NE; e++) sred[e][tid] = sc[e];
    __syncthreads();

    for (int off = 128; off > 0; off >>= 1) {
        if (tid < off) {
#pragma unroll
            for (int e = 0; e < NE; e++) sred[e][tid] += sred[e][tid + off];
        }
        __syncthreads();
    }
    if (tid == 0) {
        int best = 0;
        float bv = sred[0][0];
#pragma unroll
        for (int e = 1; e < NE; e++) {
            if (sred[e][0] > bv) { bv = sred[e][0]; best = e; }  // first-max tie-break
        }
        g_win[tok] = best;
    }

    // u[tok, e, r] = sum_d xs[d] * W_in[e, d, r]; 128 outputs, 2 threads each
    const int j    = tid & 127;           // output index: e*32 + r
    const int half = tid >> 7;            // which half of d-range
    const int e    = j >> 5;
    const int r    = j & 31;
    const float* w = W_in + (size_t)e * Dm * Rr + r;
    float acc = 0.f;
    const int d0 = half * (Dm / 2);
#pragma unroll 4
    for (int d = d0; d < d0 + Dm / 2; d++)
        acc += xs[d] * w[(size_t)d * Rr];
    upart[tid] = acc;
    __syncthreads();
    if (tid < 128) g_u[tok * (NE * Rr) + j] = upart[j] + upart[j + 128];
}

// =================================================================
// Kernel B: the sequential recurrence.
// 16 warps, warp w handles (expert e = w>>2, batch b = w&3).
// Expert e's state only changes at steps where e wins -> each warp
// walks its own winning subsequence: s = tanh(u_t + s @ W_rec[e]).
// =================================================================
__global__ void recur_kernel(const float* __restrict__ W_rec) {
    __shared__ int win_s[NTOK];
    const int tid = threadIdx.x;
    for (int i = tid; i < NTOK; i += 512) win_s[i] = g_win[i];
    __syncthreads();

    const int w    = tid >> 5;
    const int lane = tid & 31;
    const int e    = w >> 2;
    const int b    = w & 3;

    float wcol[Rr];  // column `lane` of W_rec[e]: wcol[s] = W_rec[e][s][lane]
#pragma unroll
    for (int s = 0; s < Rr; s++) wcol[s] = W_rec[(e * Rr + s) * Rr + lane];

    float st = 0.f;
    for (int t = 0; t < Tt; t++) {
        const int tok = b * Tt + t;
        if (win_s[tok] == e) {   // uniform across warp
            float a0 = g_u[tok * (NE * Rr) + e * Rr + lane];
            float a1 = 0.f, a2 = 0.f, a3 = 0.f;
#pragma unroll
            for (int s = 0; s < Rr; s += 4) {
                a0 += __shfl_sync(0xffffffffu, st, s)     * wcol[s];
                a1 += __shfl_sync(0xffffffffu, st, s + 1) * wcol[s + 1];
                a2 += __shfl_sync(0xffffffffu, st, s + 2) * wcol[s + 2];
                a3 += __shfl_sync(0xffffffffu, st, s + 3) * wcol[s + 3];
            }
            st = tanhf((a0 + a1) + (a2 + a3));
            g_cand[tok * Rr + lane] = st;
        }
    }
}

// =================================================================
// Kernel C: y = cand @ W_out[winner] + x, then LayerNorm -> g_h
// one block per token, 256 threads, 3 d's per thread
// =================================================================
__global__ void out_ln_kernel(const float* __restrict__ W_out,
                              const float* __restrict__ gamma,
                              const float* __restrict__ beta) {
    __shared__ float cs[Rr];
    __shared__ float red[2][256];

    const int tok = blockIdx.x;
    const int tid = threadIdx.x;
    const int e   = g_win[tok];

    if (tid < Rr) cs[tid] = g_cand[tok * Rr + tid];
    __syncthreads();

    float y[3];
    float s = 0.f, sq = 0.f;
#pragma unroll
    for (int i = 0; i < 3; i++) {
        const int d = tid + i * 256;
        float acc = g_x[tok * Dm + d];
        const float* wo = W_out + (size_t)e * Rr * Dm + d;
#pragma unroll
        for (int r = 0; r < Rr; r++) acc += cs[r] * wo[(size_t)r * Dm];
        y[i] = acc;
        s += acc;
        sq += acc * acc;
    }
    red[0][tid] = s;
    red[1][tid] = sq;
    __syncthreads();
    for (int off = 128; off > 0; off >>= 1) {
        if (tid < off) {
            red[0][tid] += red[0][tid + off];
            red[1][tid] += red[1][tid + off];
        }
        __syncthreads();
    }
    const float mean = red[0][0] * (1.f / Dm);
    const float var  = red[1][0] * (1.f / Dm) - mean * mean;
    const float rstd = rsqrtf(var + 1e-5f);
#pragma unroll
    for (int i = 0; i < 3; i++) {
        const int d = tid + i * 256;
        g_h[tok * Dm + d] = (y[i] - mean) * rstd * gamma[d] + beta[d];
    }
}

// =================================================================
// Kernel D: logits = h @ W_emb^T via TF32 mma.sync
// M=2048, N=50257, K=768. BM=BN=128, BK=32. 8 warps, warp tile 32x64.
// =================================================================
__device__ __forceinline__ uint32_t f2tf(float x) {
    uint32_t y;
    asm("cvt.rna.tf32.f32 %0, %1;" : "=r"(y) : "f"(x));
    return y;
}

constexpr int BK  = 32;
constexpr int PAD = 36;  // padded smem row (floats), keeps float4 alignment + no bank conflicts

__global__ void __launch_bounds__(256, 2)
gemm_logits_kernel(const float* __restrict__ Wemb, float* __restrict__ out) {
    __shared__ float As[128][PAD];
    __shared__ float Bs[128][PAD];

    const int m0   = blockIdx.x * 128;
    const int n0   = blockIdx.y * 128;
    const int tid  = threadIdx.x;
    const int warp = tid >> 5;
    const int lane = tid & 31;
    const int wm   = warp & 3;   // warp row (0..3) -> 32 M-rows
    const int wn   = warp >> 2;  // warp col (0..1) -> 64 N-cols
    const int g    = lane >> 2;  // groupID
    const int t4   = lane & 3;   // threadID_in_group

    float acc[2][8][4];
#pragma unroll
    for (int i = 0; i < 2; i++)
#pragma unroll
        for (int j = 0; j < 8; j++)
#pragma unroll
            for (int k = 0; k < 4; k++) acc[i][j][k] = 0.f;

    for (int k0 = 0; k0 < Dm; k0 += BK) {
        // load A tile (h) : 128x32, tf32-rounded at store time
#pragma unroll
        for (int i = 0; i < 4; i++) {
            const int idx = tid * 4 + i * 1024;
            const int r = idx >> 5, c = idx & 31;
            float4 v = *(const float4*)(g_h + (size_t)(m0 + r) * Dm + k0 + c);
            As[r][c]     = __uint_as_float(f2tf(v.x));
            As[r][c + 1] = __uint_as_float(f2tf(v.y));
            As[r][c + 2] = __uint_as_float(f2tf(v.z));
            As[r][c + 3] = __uint_as_float(f2tf(v.w));
        }
        // load B tile (W_emb rows = vocab) with N guard
#pragma unroll
        for (int i = 0; i < 4; i++) {
            const int idx = tid * 4 + i * 1024;
            const int r = idx >> 5, c = idx & 31;
            const int n = n0 + r;
            float4 v = make_float4(0.f, 0.f, 0.f, 0.f);
            if (n < NV) v = *(const float4*)(Wemb + (size_t)n * Dm + k0 + c);
            Bs[r][c]     = __uint_as_float(f2tf(v.x));
            Bs[r][c + 1] = __uint_as_float(f2tf(v.y));
            Bs[r][c + 2] = __uint_as_float(f2tf(v.z));
            Bs[r][c + 3] = __uint_as_float(f2tf(v.w));
        }
        __syncthreads();

#pragma unroll
        for (int k8 = 0; k8 < 4; k8++) {
            const int kb = k8 * 8;
            uint32_t af[2][4];
#pragma unroll
            for (int mt = 0; mt < 2; mt++) {
                const int row = wm * 32 + mt * 16;
                af[mt][0] = __float_as_uint(As[row + g][kb + t4]);
                af[mt][1] = __float_as_uint(As[row + g + 8][kb + t4]);
                af[mt][2] = __float_as_uint(As[row + g][kb + t4 + 4]);
                af[mt][3] = __float_as_uint(As[row + g + 8][kb + t4 + 4]);
            }
            uint32_t bf[8][2];
#pragma unroll
            for (int nt = 0; nt < 8; nt++) {
                const int col = wn * 64 + nt * 8 + g;
                bf[nt][0] = __float_as_uint(Bs[col][kb + t4]);
                bf[nt][1] = __float_as_uint(Bs[col][kb + t4 + 4]);
            }
#pragma unroll
            for (int mt = 0; mt < 2; mt++)
#pragma unroll
                for (int nt = 0; nt < 8; nt++) {
                    asm volatile(
                        "mma.sync.aligned.m16n8k8.row.col.f32.tf32.tf32.f32 "
                        "{%0,%1,%2,%3}, {%4,%5,%6,%7}, {%8,%9}, {%0,%1,%2,%3};\n"
                        : "+f"(acc[mt][nt][0]), "+f"(acc[mt][nt][1]),
                          "+f"(acc[mt][nt][2]), "+f"(acc[mt][nt][3])
                        : "r"(af[mt][0]), "r"(af[mt][1]), "r"(af[mt][2]), "r"(af[mt][3]),
                          "r"(bf[nt][0]), "r"(bf[nt][1]));
                }
        }
        __syncthreads();
    }

    // epilogue (row stride 50257 floats is odd -> scalar stores, guarded)
#pragma unroll
    for (int mt = 0; mt < 2; mt++) {
        const int row0 = m0 + wm * 32 + mt * 16 + g;
#pragma unroll
        for (int nt = 0; nt < 8; nt++) {
            const int col = n0 + wn * 64 + nt * 8 + 2 * t4;
            if (col < NV) {
                out[(size_t)row0 * NV + col]       = acc[mt][nt][0];
                out[(size_t)(row0 + 8) * NV + col] = acc[mt][nt][2];
                if (col + 1 < NV) {
                    out[(size_t)row0 * NV + col + 1]       = acc[mt][nt][1];
                    out[(size_t)(row0 + 8) * NV + col + 1] = acc[mt][nt][3];
                }
            }
        }
    }
}

// =================================================================
// launch
// =================================================================
extern "C" void kernel_launch(void* const* d_in, const int* in_sizes, int n_in,
                              void* d_out, int out_size) {
    const int*   idx   = (const int*)d_in[0];
    const float* W_emb = (const float*)d_in[1];
    const float* G     = (const float*)d_in[2];
    const float* W_in  = (const float*)d_in[3];
    const float* W_rec = (const float*)d_in[4];
    const float* W_out = (const float*)d_in[5];
    const float* gamma = (const float*)d_in[6];
    const float* beta  = (const float*)d_in[7];
    float* out = (float*)d_out;

    embed_route_kernel<<<NTOK, 256>>>(idx, W_emb, G, W_in);
    recur_kernel<<<1, 512>>>(W_rec);
    out_ln_kernel<<<NTOK, 256>>>(W_out, gamma, beta);

    dim3 grid(NTOK / 128, (NV + 127) / 128);  // x = M-tiles so same-N blocks co-schedule (L2 reuse of W_emb)
    gemm_logits_kernel<<<grid, 256>>>(W_emb, out);
}

// round 4
// speedup vs baseline: 1.1781x; 1.1781x over previous
#include <cuda_runtime.h>
#include <cstdint>

// ---------------- problem constants ----------------
constexpr int Dm    = 768;     // d_model
constexpr int NE    = 4;       // experts
constexpr int Rr    = 32;      // rank
constexpr int Bb    = 4;       // batch
constexpr int Tt    = 512;     // seq len
constexpr int NTOK  = Bb * Tt; // 2048
constexpr int NV    = 50257;   // vocab
constexpr int NVPAD = 50432;   // 197 * 256

constexpr int BM = 128, BN = 256;          // CTA tile
constexpr int NCHUNK = Dm / 32;            // 24 K-chunks of 32 floats
constexpr int MBLK = NTOK / BM;            // 16
constexpr int NBLK = NVPAD / BN;           // 197

// ---------------- scratch (no allocations allowed) ----------------
__device__ float  g_x[NTOK * Dm];                    // embedded tokens
__device__ float  g_u[NTOK * NE * Rr];               // x @ W_in (all experts)
__device__ float  g_cand[NTOK * Rr];                 // winner cand per token
__device__ float  g_h[NTOK * Dm];                    // layernormed residual (fp32)
__device__ int    g_win[NTOK];                       // winner expert per token
// permuted, tf32-rounded operands in MMA-fragment order:
// A tile (mblk,c): 1024 float4, layout [k8][m16][r8][t4]
__device__ float4 g_hp[(size_t)MBLK * NCHUNK * 1024];
// B tile (nblk,c): 2048 float4, layout [k8][col][t4pair]
__device__ float4 g_Wp[(size_t)NBLK * NCHUNK * 2048];

// ---------------- helpers ----------------
__device__ __forceinline__ uint32_t f2tf(float x) {
    uint32_t y;
    asm("cvt.rna.tf32.f32 %0, %1;" : "=r"(y) : "f"(x));
    return y;
}
__device__ __forceinline__ float tfr(float x) { return __uint_as_float(f2tf(x)); }
__device__ __forceinline__ uint32_t smem_u32(const void* p) {
    uint32_t a;
    asm("{ .reg .u64 t; cvta.to.shared.u64 t, %1; cvt.u32.u64 %0, t; }" : "=r"(a) : "l"(p));
    return a;
}
__device__ __forceinline__ void cp16(uint32_t s, const void* g) {
    asm volatile("{ .reg .u64 gg; cvta.to.global.u64 gg, %1; cp.async.cg.shared.global [%0], [gg], 16; }"
                 :: "r"(s), "l"(g));
}
#define CP_COMMIT() asm volatile("cp.async.commit_group;" ::: "memory")
#define CP_WAIT(n)  asm volatile("cp.async.wait_group %0;" :: "n"(n) : "memory")
#define LDS128(r0, r1, r2, r3, a) \
    asm volatile("ld.shared.v4.b32 {%0,%1,%2,%3}, [%4];" \
                 : "=r"(r0), "=r"(r1), "=r"(r2), "=r"(r3) : "r"(a))
#define LDS64(r0, r1, a) \
    asm volatile("ld.shared.v2.b32 {%0,%1}, [%2];" : "=r"(r0), "=r"(r1) : "r"(a))

// =================================================================
// Kernel W: W_emb -> tf32-rounded, fragment-permuted g_Wp
// grid (NCHUNK, NBLK), 256 threads; thread = col within 256-col tile
// =================================================================
__global__ void perm_wemb_kernel(const float* __restrict__ W) {
    const int c    = blockIdx.x;
    const int nblk = blockIdx.y;
    const int col  = threadIdx.x;
    const int gcol = nblk * 256 + col;

    float v[32];
    if (gcol < NV) {
        const float4* src = (const float4*)(W + (size_t)gcol * Dm + c * 32);
#pragma unroll
        for (int i = 0; i < 8; i++) {
            float4 q = src[i];
            v[i * 4]     = tfr(q.x);
            v[i * 4 + 1] = tfr(q.y);
            v[i * 4 + 2] = tfr(q.z);
            v[i * 4 + 3] = tfr(q.w);
        }
    } else {
#pragma unroll
        for (int i = 0; i < 32; i++) v[i] = 0.f;
    }
    float4* dst = g_Wp + ((size_t)nblk * NCHUNK + c) * 2048;
#pragma unroll
    for (int k8 = 0; k8 < 4; k8++) {
        const float* w = v + k8 * 8;
        dst[(k8 * 256 + col) * 2]     = make_float4(w[0], w[4], w[1], w[5]);
        dst[(k8 * 256 + col) * 2 + 1] = make_float4(w[2], w[6], w[3], w[7]);
    }
}

// =================================================================
// Kernel A: embedding gather + routing argmax + u = x @ W_in
// =================================================================
__global__ void embed_route_kernel(const int* __restrict__ idx,
                                   const float* __restrict__ W_emb,
                                   const float* __restrict__ G,
                                   const float* __restrict__ W_in) {
    __shared__ float xs[Dm];
    __shared__ float sred[NE][256];
    __shared__ float upart[256];

    const int tok = blockIdx.x;
    const int tid = threadIdx.x;
    const int id  = idx[tok];

    float sc[NE] = {0.f, 0.f, 0.f, 0.f};
    for (int d = tid; d < Dm; d += 256) {
        float v = W_emb[(size_t)id * Dm + d];
        xs[d] = v;
        g_x[tok * Dm + d] = v;
#pragma unroll
        for (int e = 0; e < NE; e++) sc[e] += v * G[e * Dm + d];
    }
#pragma unroll
    for (int e = 0; e < NE; e++) sred[e][tid] = sc[e];
    __syncthreads();
    for (int off = 128; off > 0; off >>= 1) {
        if (tid < off) {
#pragma unroll
            for (int e = 0; e < NE; e++) sred[e][tid] += sred[e][tid + off];
        }
        __syncthreads();
    }
    if (tid == 0) {
        int best = 0;
        float bv = sred[0][0];
#pragma unroll
        for (int e = 1; e < NE; e++)
            if (sred[e][0] > bv) { bv = sred[e][0]; best = e; }
        g_win[tok] = best;
    }

    const int j    = tid & 127;
    const int half = tid >> 7;
    const int e    = j >> 5;
    const int r    = j & 31;
    const float* w = W_in + (size_t)e * Dm * Rr + r;
    float acc = 0.f;
    const int d0 = half * (Dm / 2);
#pragma unroll 4
    for (int d = d0; d < d0 + Dm / 2; d++)
        acc += xs[d] * w[(size_t)d * Rr];
    upart[tid] = acc;
    __syncthreads();
    if (tid < 128) g_u[tok * (NE * Rr) + j] = upart[j] + upart[j + 128];
}

// =================================================================
// Kernel B: sequential recurrence with per-warp winner lists + prefetch
// =================================================================
__global__ void recur_kernel(const float* __restrict__ W_rec) {
    __shared__ int win_s[NTOK];
    __shared__ int lists[16][512];
    const int tid = threadIdx.x;
    for (int i = tid; i < NTOK; i += 512) win_s[i] = g_win[i];
    __syncthreads();

    const int w = tid >> 5, lane = tid & 31;
    const int e = w >> 2, b = w & 3;

    // build this warp's winning-token list (all lanes compute identically)
    int n = 0;
    for (int base = 0; base < Tt; base += 32) {
        unsigned m = __ballot_sync(0xffffffffu, win_s[b * Tt + base + lane] == e);
        while (m) {
            int i = __ffs(m) - 1;
            m &= m - 1;
            lists[w][n++] = base + i;
        }
    }

    float wcol[Rr];
#pragma unroll
    for (int s = 0; s < Rr; s++) wcol[s] = W_rec[(e * Rr + s) * Rr + lane];

    float st = 0.f;
    float unext = 0.f;
    if (n > 0) unext = g_u[(b * Tt + lists[w][0]) * (NE * Rr) + e * Rr + lane];
    for (int i = 0; i < n; i++) {
        const float ucur = unext;
        if (i + 1 < n)
            unext = g_u[(b * Tt + lists[w][i + 1]) * (NE * Rr) + e * Rr + lane];
        float a0 = ucur, a1 = 0.f, a2 = 0.f, a3 = 0.f;
#pragma unroll
        for (int s = 0; s < Rr; s += 4) {
            a0 += __shfl_sync(0xffffffffu, st, s)     * wcol[s];
            a1 += __shfl_sync(0xffffffffu, st, s + 1) * wcol[s + 1];
            a2 += __shfl_sync(0xffffffffu, st, s + 2) * wcol[s + 2];
            a3 += __shfl_sync(0xffffffffu, st, s + 3) * wcol[s + 3];
        }
        st = tanhf((a0 + a1) + (a2 + a3));
        g_cand[(b * Tt + lists[w][i]) * Rr + lane] = st;
    }
}

// =================================================================
// Kernel C: y = cand @ W_out[winner] + x, LayerNorm -> g_h (fp32)
// =================================================================
__global__ void out_ln_kernel(const float* __restrict__ W_out,
                              const float* __restrict__ gamma,
                              const float* __restrict__ beta) {
    __shared__ float cs[Rr];
    __shared__ float red[2][256];

    const int tok = blockIdx.x;
    const int tid = threadIdx.x;
    const int e   = g_win[tok];

    if (tid < Rr) cs[tid] = g_cand[tok * Rr + tid];
    __syncthreads();

    float y[3];
    float s = 0.f, sq = 0.f;
#pragma unroll
    for (int i = 0; i < 3; i++) {
        const int d = tid + i * 256;
        float acc = g_x[tok * Dm + d];
        const float* wo = W_out + (size_t)e * Rr * Dm + d;
#pragma unroll
        for (int r = 0; r < Rr; r++) acc += cs[r] * wo[(size_t)r * Dm];
        y[i] = acc;
        s += acc;
        sq += acc * acc;
    }
    red[0][tid] = s;
    red[1][tid] = sq;
    __syncthreads();
    for (int off = 128; off > 0; off >>= 1) {
        if (tid < off) {
            red[0][tid] += red[0][tid + off];
            red[1][tid] += red[1][tid + off];
        }
        __syncthreads();
    }
    const float mean = red[0][0] * (1.f / Dm);
    const float var  = red[1][0] * (1.f / Dm) - mean * mean;
    const float rstd = rsqrtf(var + 1e-5f);
#pragma unroll
    for (int i = 0; i < 3; i++) {
        const int d = tid + i * 256;
        g_h[tok * Dm + d] = (y[i] - mean) * rstd * gamma[d] + beta[d];
    }
}

// =================================================================
// Kernel P: h -> tf32-rounded, fragment-permuted g_hp
// grid (NCHUNK, MBLK), 256 threads
// float4 = (A[r][kb+t4], A[r+8][kb+t4], A[r][kb+t4+4], A[r+8][kb+t4+4])
// =================================================================
__global__ void perm_h_kernel() {
    const int c    = blockIdx.x;
    const int mblk = blockIdx.y;
    const int j    = threadIdx.x;
    const int m16  = j >> 5;
    const int r8   = (j >> 2) & 7;
    const int t4   = j & 3;
    const int r0   = mblk * 128 + m16 * 16 + r8;
    const int kb0  = c * 32;

    float4* dst = g_hp + ((size_t)mblk * NCHUNK + c) * 1024;
#pragma unroll
    for (int k8 = 0; k8 < 4; k8++) {
        const int kb = kb0 + k8 * 8;
        float4 o;
        o.x = tfr(g_h[(size_t)r0 * Dm + kb + t4]);
        o.y = tfr(g_h[(size_t)(r0 + 8) * Dm + kb + t4]);
        o.z = tfr(g_h[(size_t)r0 * Dm + kb + t4 + 4]);
        o.w = tfr(g_h[(size_t)(r0 + 8) * Dm + kb + t4 + 4]);
        dst[((k8 * 8 + m16) * 8 + r8) * 4 + t4] = o;
    }
}

// =================================================================
// Kernel D: logits = h @ W_emb^T via mma.sync tf32
// CTA 128x256, 8 warps (2 wm x 4 wn), warp tile 64x64, 3-stage cp.async
// =================================================================
constexpr int STAGE_BYTES = 49152;  // 16KB A + 32KB B
constexpr int SM_TOT      = 3 * STAGE_BYTES;

__global__ void __launch_bounds__(256, 1)
gemm_tc_kernel(float* __restrict__ out) {
    extern __shared__ char smem[];
    const uint32_t sbase = smem_u32(smem);
    const int tid  = threadIdx.x;
    const int warp = tid >> 5;
    const int lane = tid & 31;
    const int wm   = warp & 1;    // 2 row-warps: 64 rows each
    const int wn   = warp >> 1;   // 4 col-warps: 64 cols each
    const int g    = lane >> 2;
    const int t4   = lane & 3;
    const int mblk = blockIdx.x;
    const int nblk = blockIdx.y;

    const float4* gA = g_hp + (size_t)mblk * NCHUNK * 1024;
    const float4* gB = g_Wp + (size_t)nblk * NCHUNK * 2048;

    auto load_stage = [&](int s, int c) {
        const uint32_t sA = sbase + s * STAGE_BYTES;
        const uint32_t sB = sA + 16384;
        const float4* a = gA + c * 1024;
        const float4* b = gB + c * 2048;
#pragma unroll
        for (int t = 0; t < 4; t++) {
            const int i = tid + t * 256;
            cp16(sA + i * 16, a + i);
        }
#pragma unroll
        for (int t = 0; t < 8; t++) {
            const int i = tid + t * 256;
            cp16(sB + i * 16, b + i);
        }
        CP_COMMIT();
    };

    load_stage(0, 0);
    load_stage(1, 1);

    float acc[4][8][4];
#pragma unroll
    for (int mt = 0; mt < 4; mt++)
#pragma unroll
        for (int nt = 0; nt < 8; nt++)
#pragma unroll
            for (int k = 0; k < 4; k++) acc[mt][nt][k] = 0.f;

    // per-warp smem fragment base offsets
    const uint32_t aoff = (wm * 4) * 512 + g * 64 + t4 * 16;          // + k8*4096 + mt*512
    const uint32_t boff = 16384 + wn * 2048 + g * 32 + t4 * 8;        // + k8*8192 + nt*256

    for (int c = 0; c < NCHUNK; c++) {
        if (c == NCHUNK - 1) { CP_WAIT(0); } else { CP_WAIT(1); }
        __syncthreads();
        if (c + 2 < NCHUNK) load_stage((c + 2) % 3, c + 2);

        const uint32_t sS = sbase + (c % 3) * STAGE_BYTES;
#pragma unroll
        for (int k8 = 0; k8 < 4; k8++) {
            uint32_t af[4][4];
#pragma unroll
            for (int mt = 0; mt < 4; mt++)
                LDS128(af[mt][0], af[mt][1], af[mt][2], af[mt][3],
                       sS + aoff + k8 * 4096 + mt * 512);
            uint32_t bfr[8][2];
#pragma unroll
            for (int nt = 0; nt < 8; nt++)
                LDS64(bfr[nt][0], bfr[nt][1],
                      sS + boff + k8 * 8192 + nt * 256);
#pragma unroll
            for (int mt = 0; mt < 4; mt++)
#pragma unroll
                for (int nt = 0; nt < 8; nt++) {
                    asm volatile(
                        "mma.sync.aligned.m16n8k8.row.col.f32.tf32.tf32.f32 "
                        "{%0,%1,%2,%3}, {%4,%5,%6,%7}, {%8,%9}, {%0,%1,%2,%3};\n"
                        : "+f"(acc[mt][nt][0]), "+f"(acc[mt][nt][1]),
                          "+f"(acc[mt][nt][2]), "+f"(acc[mt][nt][3])
                        : "r"(af[mt][0]), "r"(af[mt][1]), "r"(af[mt][2]), "r"(af[mt][3]),
                          "r"(bfr[nt][0]), "r"(bfr[nt][1]));
                }
        }
    }

    // epilogue: direct register -> gmem stores (guard last n-tile)
    const int m0 = mblk * BM;
    const int n0 = nblk * BN;
#pragma unroll
    for (int mt = 0; mt < 4; mt++) {
        const int row0 = m0 + wm * 64 + mt * 16 + g;
#pragma unroll
        for (int nt = 0; nt < 8; nt++) {
            const int col = n0 + wn * 64 + nt * 8 + t4 * 2;
            if (col + 1 < NV) {
                out[(size_t)row0 * NV + col]           = acc[mt][nt][0];
                out[(size_t)row0 * NV + col + 1]       = acc[mt][nt][1];
                out[(size_t)(row0 + 8) * NV + col]     = acc[mt][nt][2];
                out[(size_t)(row0 + 8) * NV + col + 1] = acc[mt][nt][3];
            } else if (col < NV) {
                out[(size_t)row0 * NV + col]       = acc[mt][nt][0];
                out[(size_t)(row0 + 8) * NV + col] = acc[mt][nt][2];
            }
        }
    }
}

// =================================================================
// launch
// =================================================================
extern "C" void kernel_launch(void* const* d_in, const int* in_sizes, int n_in,
                              void* d_out, int out_size) {
    const int*   idx   = (const int*)d_in[0];
    const float* W_emb = (const float*)d_in[1];
    const float* G     = (const float*)d_in[2];
    const float* W_in  = (const float*)d_in[3];
    const float* W_rec = (const float*)d_in[4];
    const float* W_out = (const float*)d_in[5];
    const float* gamma = (const float*)d_in[6];
    const float* beta  = (const float*)d_in[7];
    float* out = (float*)d_out;

    cudaFuncSetAttribute(gemm_tc_kernel,
                         cudaFuncAttributeMaxDynamicSharedMemorySize, SM_TOT);

    perm_wemb_kernel<<<dim3(NCHUNK, NBLK), 256>>>(W_emb);
    embed_route_kernel<<<NTOK, 256>>>(idx, W_emb, G, W_in);
    recur_kernel<<<1, 512>>>(W_rec);
    out_ln_kernel<<<NTOK, 256>>>(W_out, gamma, beta);
    perm_h_kernel<<<dim3(NCHUNK, MBLK), 256>>>();

    dim3 grid(MBLK, NBLK);  // x = M fastest => same-B blocks co-resident (L2 reuse)
    gemm_tc_kernel<<<grid, 256, SM_TOT>>>(out);
}

// round 5
// speedup vs baseline: 1.1894x; 1.0096x over previous
#include <cuda_runtime.h>
#include <cstdint>

// ---------------- problem constants ----------------
constexpr int Dm    = 768;
constexpr int NE    = 4;
constexpr int Rr    = 32;
constexpr int Bb    = 4;
constexpr int Tt    = 512;
constexpr int NTOK  = Bb * Tt;   // 2048
constexpr int NV    = 50257;
constexpr int NVPAD = 50432;     // 197 * 256

constexpr int BM = 128, BN = 256;
constexpr int NCHUNK = Dm / 32;  // 24
constexpr int MBLK = NTOK / BM;  // 16
constexpr int NBLK = NVPAD / BN; // 197

// ---------------- scratch ----------------
__device__ float  g_x[NTOK * Dm];
__device__ float  g_u[NTOK * NE * Rr];
__device__ float  g_cand[NTOK * Rr];
__device__ int    g_win[NTOK];
// A tile (mblk,c): 1024 float4, layout [k8][m16][r8][t4] -> (r, r+8, r(+4k), r+8(+4k))
__device__ float4 g_hp[(size_t)MBLK * NCHUNK * 1024];
// B tile (nblk,c): 2048 float4, paired layout [k8][wn][pr][g][t4] = (colA k, colA k+4, colB k, colB k+4)
__device__ float4 g_Wp[(size_t)NBLK * NCHUNK * 2048];

// ---------------- helpers ----------------
__device__ __forceinline__ uint32_t f2tf(float x) {
    uint32_t y;
    asm("cvt.rna.tf32.f32 %0, %1;" : "=r"(y) : "f"(x));
    return y;
}
__device__ __forceinline__ float tfr(float x) { return __uint_as_float(f2tf(x)); }
__device__ __forceinline__ uint32_t smem_u32(const void* p) {
    uint32_t a;
    asm("{ .reg .u64 t; cvta.to.shared.u64 t, %1; cvt.u32.u64 %0, t; }" : "=r"(a) : "l"(p));
    return a;
}
__device__ __forceinline__ void cp16(uint32_t s, const void* g) {
    asm volatile("{ .reg .u64 gg; cvta.to.global.u64 gg, %1; cp.async.cg.shared.global [%0], [gg], 16; }"
                 :: "r"(s), "l"(g));
}
#define CP_COMMIT() asm volatile("cp.async.commit_group;" ::: "memory")
#define CP_WAIT(n)  asm volatile("cp.async.wait_group %0;" :: "n"(n) : "memory")
#define LDS128(r0, r1, r2, r3, a) \
    asm volatile("ld.shared.v4.b32 {%0,%1,%2,%3}, [%4];" \
                 : "=r"(r0), "=r"(r1), "=r"(r2), "=r"(r3) : "r"(a))

// =================================================================
// Kernel W: W_emb -> tf32-rounded, pair-permuted g_Wp
// grid (NCHUNK, NBLK), 256 threads; thread = col in 256-col tile
// =================================================================
__global__ void perm_wemb_kernel(const float* __restrict__ W) {
    const int c    = blockIdx.x;
    const int nblk = blockIdx.y;
    const int col  = threadIdx.x;
    const int gcol = nblk * 256 + col;

    float v[32];
    if (gcol < NV) {
        const float4* src = (const float4*)(W + (size_t)gcol * Dm + c * 32);
#pragma unroll
        for (int i = 0; i < 8; i++) {
            float4 q = src[i];
            v[i * 4]     = tfr(q.x);
            v[i * 4 + 1] = tfr(q.y);
            v[i * 4 + 2] = tfr(q.z);
            v[i * 4 + 3] = tfr(q.w);
        }
    } else {
#pragma unroll
        for (int i = 0; i < 32; i++) v[i] = 0.f;
    }
    // col = wn*64 + pr*16 + h*8 + g
    const int wn = col >> 6, pr = (col >> 4) & 3, h = (col >> 3) & 1, g = col & 7;
    float2* dst = (float2*)(g_Wp + ((size_t)nblk * NCHUNK + c) * 2048);
#pragma unroll
    for (int k8 = 0; k8 < 4; k8++) {
#pragma unroll
        for (int t4 = 0; t4 < 4; t4++) {
            const int I = ((k8 * 4 + wn) * 4 + pr) * 32 + g * 4 + t4;
            dst[I * 2 + h] = make_float2(v[k8 * 8 + t4], v[k8 * 8 + t4 + 4]);
        }
    }
}

// =================================================================
// Kernel A: embedding gather + routing argmax + u = x @ W_in
// =================================================================
__global__ void embed_route_kernel(const int* __restrict__ idx,
                                   const float* __restrict__ W_emb,
                                   const float* __restrict__ G,
                                   const float* __restrict__ W_in) {
    __shared__ float xs[Dm];
    __shared__ float sred[NE][256];
    __shared__ float upart[256];

    const int tok = blockIdx.x;
    const int tid = threadIdx.x;
    const int id  = idx[tok];

    float sc[NE] = {0.f, 0.f, 0.f, 0.f};
    for (int d = tid; d < Dm; d += 256) {
        float v = W_emb[(size_t)id * Dm + d];
        xs[d] = v;
        g_x[tok * Dm + d] = v;
#pragma unroll
        for (int e = 0; e < NE; e++) sc[e] += v * G[e * Dm + d];
    }
#pragma unroll
    for (int e = 0; e < NE; e++) sred[e][tid] = sc[e];
    __syncthreads();
    for (int off = 128; off > 0; off >>= 1) {
        if (tid < off) {
#pragma unroll
            for (int e = 0; e < NE; e++) sred[e][tid] += sred[e][tid + off];
        }
        __syncthreads();
    }
    if (tid == 0) {
        int best = 0;
        float bv = sred[0][0];
#pragma unroll
        for (int e = 1; e < NE; e++)
            if (sred[e][0] > bv) { bv = sred[e][0]; best = e; }
        g_win[tok] = best;
    }

    const int j    = tid & 127;
    const int half = tid >> 7;
    const int e    = j >> 5;
    const int r    = j & 31;
    const float* w = W_in + (size_t)e * Dm * Rr + r;
    float acc = 0.f;
    const int d0 = half * (Dm / 2);
#pragma unroll 4
    for (int d = d0; d < d0 + Dm / 2; d++)
        acc += xs[d] * w[(size_t)d * Rr];
    upart[tid] = acc;
    __syncthreads();
    if (tid < 128) g_u[tok * (NE * Rr) + j] = upart[j] + upart[j + 128];
}

// =================================================================
// Kernel B: sequential recurrence (winner lists + u prefetch)
// =================================================================
__global__ void recur_kernel(const float* __restrict__ W_rec) {
    __shared__ int win_s[NTOK];
    __shared__ int lists[16][512];
    const int tid = threadIdx.x;
    for (int i = tid; i < NTOK; i += 512) win_s[i] = g_win[i];
    __syncthreads();

    const int w = tid >> 5, lane = tid & 31;
    const int e = w >> 2, b = w & 3;

    int n = 0;
    for (int base = 0; base < Tt; base += 32) {
        unsigned m = __ballot_sync(0xffffffffu, win_s[b * Tt + base + lane] == e);
        while (m) {
            int i = __ffs(m) - 1;
            m &= m - 1;
            lists[w][n++] = base + i;
        }
    }

    float wcol[Rr];
#pragma unroll
    for (int s = 0; s < Rr; s++) wcol[s] = W_rec[(e * Rr + s) * Rr + lane];

    float st = 0.f;
    float unext = 0.f;
    if (n > 0) unext = g_u[(b * Tt + lists[w][0]) * (NE * Rr) + e * Rr + lane];
    for (int i = 0; i < n; i++) {
        const float ucur = unext;
        if (i + 1 < n)
            unext = g_u[(b * Tt + lists[w][i + 1]) * (NE * Rr) + e * Rr + lane];
        float a0 = ucur, a1 = 0.f, a2 = 0.f, a3 = 0.f;
#pragma unroll
        for (int s = 0; s < Rr; s += 4) {
            a0 += __shfl_sync(0xffffffffu, st, s)     * wcol[s];
            a1 += __shfl_sync(0xffffffffu, st, s + 1) * wcol[s + 1];
            a2 += __shfl_sync(0xffffffffu, st, s + 2) * wcol[s + 2];
            a3 += __shfl_sync(0xffffffffu, st, s + 3) * wcol[s + 3];
        }
        st = tanhf((a0 + a1) + (a2 + a3));
        g_cand[(b * Tt + lists[w][i]) * Rr + lane] = st;
    }
}

// =================================================================
// Kernel C: y = cand @ W_out[winner] + x, LayerNorm, tf32-round,
//           write DIRECTLY into fragment-permuted g_hp (fuses perm_h)
// =================================================================
__global__ void out_ln_kernel(const float* __restrict__ W_out,
                              const float* __restrict__ gamma,
                              const float* __restrict__ beta) {
    __shared__ float cs[Rr];
    __shared__ float red[2][256];

    const int tok = blockIdx.x;
    const int tid = threadIdx.x;
    const int e   = g_win[tok];

    if (tid < Rr) cs[tid] = g_cand[tok * Rr + tid];
    __syncthreads();

    float y[3];
    float s = 0.f, sq = 0.f;
#pragma unroll
    for (int i = 0; i < 3; i++) {
        const int d = tid + i * 256;
        float acc = g_x[tok * Dm + d];
        const float* wo = W_out + (size_t)e * Rr * Dm + d;
#pragma unroll
        for (int r = 0; r < Rr; r++) acc += cs[r] * wo[(size_t)r * Dm];
        y[i] = acc;
        s += acc;
        sq += acc * acc;
    }
    red[0][tid] = s;
    red[1][tid] = sq;
    __syncthreads();
    for (int off = 128; off > 0; off >>= 1) {
        if (tid < off) {
            red[0][tid] += red[0][tid + off];
            red[1][tid] += red[1][tid + off];
        }
        __syncthreads();
    }
    const float mean = red[0][0] * (1.f / Dm);
    const float var  = red[1][0] * (1.f / Dm) - mean * mean;
    const float rstd = rsqrtf(var + 1e-5f);

    const int mblk = tok >> 7;
    const int rr   = tok & 127;
    const int m16  = rr >> 4;
    const int w16  = rr & 15;
    const int r8   = w16 & 7;
    const int halfr = w16 >> 3;
#pragma unroll
    for (int i = 0; i < 3; i++) {
        const int d = tid + i * 256;
        const float hv = tfr((y[i] - mean) * rstd * gamma[d] + beta[d]);
        const int c  = d >> 5, rem = d & 31;
        const int k8 = rem >> 3, kk = rem & 7;
        const int t4 = kk & 3, hi = kk >> 2;
        const int fidx = ((k8 * 8 + m16) * 8 + r8) * 4 + t4;
        float* fp = (float*)(g_hp + ((size_t)mblk * NCHUNK + c) * 1024 + fidx);
        fp[hi * 2 + halfr] = hv;
    }
}

// =================================================================
// Kernel D: logits = h @ W_emb^T, mma.sync tf32
// CTA 128x256, 8 warps (2 wm x 4 wn), warp tile 64x64.
// 4-stage cp.async ring + per-k8 fragment ping-pong registers.
// =================================================================
constexpr int STAGE_BYTES = 49152;   // 16KB A + 32KB B
constexpr int SM_TOT      = 4 * STAGE_BYTES;  // 192KB

__global__ void __launch_bounds__(256, 1)
gemm_tc_kernel(float* __restrict__ out) {
    extern __shared__ char smem[];
    const uint32_t sbase = smem_u32(smem);
    const int tid  = threadIdx.x;
    const int warp = tid >> 5;
    const int lane = tid & 31;
    const int wm   = warp & 1;
    const int wn   = warp >> 1;
    const int g    = lane >> 2;
    const int t4   = lane & 3;
    const int mblk = blockIdx.x;
    const int nblk = blockIdx.y;

    const float4* gA = g_hp + (size_t)mblk * NCHUNK * 1024;
    const float4* gB = g_Wp + (size_t)nblk * NCHUNK * 2048;

    auto load_stage = [&](int slot, int c) {
        const uint32_t sA = sbase + slot * STAGE_BYTES;
        const uint32_t sB = sA + 16384;
        const float4* a = gA + c * 1024;
        const float4* b = gB + c * 2048;
#pragma unroll
        for (int t = 0; t < 4; t++) cp16(sA + (tid + t * 256) * 16, a + tid + t * 256);
#pragma unroll
        for (int t = 0; t < 8; t++) cp16(sB + (tid + t * 256) * 16, b + tid + t * 256);
        CP_COMMIT();
    };

    load_stage(0, 0);
    load_stage(1, 1);
    load_stage(2, 2);

    float acc[4][8][4];
#pragma unroll
    for (int mt = 0; mt < 4; mt++)
#pragma unroll
        for (int nt = 0; nt < 8; nt++)
#pragma unroll
            for (int k = 0; k < 4; k++) acc[mt][nt][k] = 0.f;

    // per-warp fragment base offsets within a stage
    const uint32_t aoff = (wm * 4) * 512 + g * 64 + t4 * 16;       // + k8*4096 + mt*512
    const uint32_t boff = 16384 + wn * 2048 + g * 64 + t4 * 16;    // + k8*8192 + pr*512

    uint32_t af[2][16], bf[2][16];

    auto lds_frags = [&](int p, uint32_t sS, int k8) {
#pragma unroll
        for (int mt = 0; mt < 4; mt++)
            LDS128(af[p][mt * 4], af[p][mt * 4 + 1], af[p][mt * 4 + 2], af[p][mt * 4 + 3],
                   sS + aoff + k8 * 4096 + mt * 512);
#pragma unroll
        for (int pr = 0; pr < 4; pr++)
            LDS128(bf[p][pr * 4], bf[p][pr * 4 + 1], bf[p][pr * 4 + 2], bf[p][pr * 4 + 3],
                   sS + boff + k8 * 8192 + pr * 512);
    };

    auto do_mma = [&](int p) {
#pragma unroll
        for (int mt = 0; mt < 4; mt++)
#pragma unroll
            for (int nt = 0; nt < 8; nt++) {
                const int bi = (nt >> 1) * 4 + (nt & 1) * 2;
                asm volatile(
                    "mma.sync.aligned.m16n8k8.row.col.f32.tf32.tf32.f32 "
                    "{%0,%1,%2,%3}, {%4,%5,%6,%7}, {%8,%9}, {%0,%1,%2,%3};\n"
                    : "+f"(acc[mt][nt][0]), "+f"(acc[mt][nt][1]),
                      "+f"(acc[mt][nt][2]), "+f"(acc[mt][nt][3])
                    : "r"(af[p][mt * 4]), "r"(af[p][mt * 4 + 1]),
                      "r"(af[p][mt * 4 + 2]), "r"(af[p][mt * 4 + 3]),
                      "r"(bf[p][bi]), "r"(bf[p][bi + 1]));
            }
    };

#pragma unroll 1
    for (int c = 0; c < NCHUNK; c++) {
        if (c < NCHUNK - 2)      { CP_WAIT(2); }
        else if (c == NCHUNK - 2) { CP_WAIT(1); }
        else                      { CP_WAIT(0); }
        __syncthreads();
        if (c + 3 < NCHUNK) load_stage((c + 3) & 3, c + 3);

        const uint32_t sS = sbase + (c & 3) * STAGE_BYTES;
        lds_frags(0, sS, 0);
#pragma unroll
        for (int k8 = 0; k8 < 4; k8++) {
            if (k8 < 3) lds_frags((k8 + 1) & 1, sS, k8 + 1);
            do_mma(k8 & 1);
        }
    }

    const int m0 = mblk * BM;
    const int n0 = nblk * BN;
#pragma unroll
    for (int mt = 0; mt < 4; mt++) {
        const int row0 = m0 + wm * 64 + mt * 16 + g;
#pragma unroll
        for (int nt = 0; nt < 8; nt++) {
            const int col = n0 + wn * 64 + nt * 8 + t4 * 2;
            if (col + 1 < NV) {
                out[(size_t)row0 * NV + col]           = acc[mt][nt][0];
                out[(size_t)row0 * NV + col + 1]       = acc[mt][nt][1];
                out[(size_t)(row0 + 8) * NV + col]     = acc[mt][nt][2];
                out[(size_t)(row0 + 8) * NV + col + 1] = acc[mt][nt][3];
            } else if (col < NV) {
                out[(size_t)row0 * NV + col]       = acc[mt][nt][0];
                out[(size_t)(row0 + 8) * NV + col] = acc[mt][nt][2];
            }
        }
    }
}

// =================================================================
// launch
// =================================================================
extern "C" void kernel_launch(void* const* d_in, const int* in_sizes, int n_in,
                              void* d_out, int out_size) {
    const int*   idx   = (const int*)d_in[0];
    const float* W_emb = (const float*)d_in[1];
    const float* G     = (const float*)d_in[2];
    const float* W_in  = (const float*)d_in[3];
    const float* W_rec = (const float*)d_in[4];
    const float* W_out = (const float*)d_in[5];
    const float* gamma = (const float*)d_in[6];
    const float* beta  = (const float*)d_in[7];
    float* out = (float*)d_out;

    cudaFuncSetAttribute(gemm_tc_kernel,
                         cudaFuncAttributeMaxDynamicSharedMemorySize, SM_TOT);

    perm_wemb_kernel<<<dim3(NCHUNK, NBLK), 256>>>(W_emb);
    embed_route_kernel<<<NTOK, 256>>>(idx, W_emb, G, W_in);
    recur_kernel<<<1, 512>>>(W_rec);
    out_ln_kernel<<<NTOK, 256>>>(W_out, gamma, beta);

    dim3 grid(MBLK, NBLK);
    gemm_tc_kernel<<<grid, 256, SM_TOT>>>(out);
}

// round 6
// speedup vs baseline: 1.7136x; 1.4407x over previous
#include <cuda_runtime.h>
#include <cuda_fp16.h>
#include <cstdint>
#include <cstring>

// ---------------- problem constants ----------------
constexpr int Dm    = 768;
constexpr int NE    = 4;
constexpr int Rr    = 32;
constexpr int Bb    = 4;
constexpr int Tt    = 512;
constexpr int NTOK  = Bb * Tt;   // 2048
constexpr int NV    = 50257;
constexpr int NVPAD = 50432;     // 197 * 256

constexpr int BM = 128, BN = 256;
constexpr int NCHUNK = Dm / 64;  // 12 chunks of K=64
constexpr int MBLK = NTOK / BM;  // 16
constexpr int NBLK = NVPAD / BN; // 197

// ---------------- scratch ----------------
__device__ float  g_x[NTOK * Dm];
__device__ float  g_u[NTOK * NE * Rr];
__device__ float  g_cand[NTOK * Rr];
__device__ int    g_win[NTOK];
// A tiles, fp16 fragment-packed: per (mblk,c): [k16(4)][m16(8)][lane(32)] x uint4
__device__ uint4  g_hp[(size_t)MBLK * NCHUNK * 1024];
// B tiles, fp16 pair-packed: per (nblk,c): [k16(4)][wn(4)][pr(4)][lane(32)] x uint4
__device__ uint4  g_Wp[(size_t)NBLK * NCHUNK * 2048];

// ---------------- helpers ----------------
__device__ __forceinline__ uint32_t h2u(__half a, __half b) {
    __half2 t = __halves2half2(a, b);
    uint32_t u;
    memcpy(&u, &t, 4);
    return u;
}
__device__ __forceinline__ uint32_t smem_u32(const void* p) {
    uint32_t a;
    asm("{ .reg .u64 t; cvta.to.shared.u64 t, %1; cvt.u32.u64 %0, t; }" : "=r"(a) : "l"(p));
    return a;
}
__device__ __forceinline__ void cp16(uint32_t s, const void* g) {
    asm volatile("{ .reg .u64 gg; cvta.to.global.u64 gg, %1; cp.async.cg.shared.global [%0], [gg], 16; }"
                 :: "r"(s), "l"(g));
}
#define CP_COMMIT() asm volatile("cp.async.commit_group;" ::: "memory")
#define CP_WAIT(n)  asm volatile("cp.async.wait_group %0;" :: "n"(n) : "memory")
#define LDS128(r0, r1, r2, r3, a) \
    asm volatile("ld.shared.v4.b32 {%0,%1,%2,%3}, [%4];" \
                 : "=r"(r0), "=r"(r1), "=r"(r2), "=r"(r3) : "r"(a))

// =================================================================
// Kernel W: W_emb -> fp16, fragment-packed g_Wp
// grid (NCHUNK, NBLK), 256 threads; thread = col (0..255) of the tile
// m16n8k16 B frag: b0 = (k=t4*2,t4*2+1, col g), b1 = (k=8+t4*2,.., col g)
// uint4 = {b0(nt even), b1(nt even), b0(nt odd), b1(nt odd)}
// =================================================================
__global__ void perm_wemb_kernel(const float* __restrict__ W) {
    const int c    = blockIdx.x;
    const int nblk = blockIdx.y;
    const int col  = threadIdx.x;
    const int gcol = nblk * 256 + col;

    __half v[64];
    if (gcol < NV) {
        const float4* src = (const float4*)(W + (size_t)gcol * Dm + c * 64);
#pragma unroll
        for (int i = 0; i < 16; i++) {
            float4 q = src[i];
            v[i * 4]     = __float2half_rn(q.x);
            v[i * 4 + 1] = __float2half_rn(q.y);
            v[i * 4 + 2] = __float2half_rn(q.z);
            v[i * 4 + 3] = __float2half_rn(q.w);
        }
    } else {
#pragma unroll
        for (int i = 0; i < 64; i++) v[i] = __float2half_rn(0.f);
    }
    const int wn = col >> 6, pr = (col >> 4) & 3, h = (col >> 3) & 1, g = col & 7;
#pragma unroll
    for (int k16 = 0; k16 < 4; k16++) {
#pragma unroll
        for (int t4 = 0; t4 < 4; t4++) {
            const size_t idx =
                ((((size_t)(nblk * NCHUNK + c) * 4 + k16) * 4 + wn) * 4 + pr) * 32 + g * 4 + t4;
            uint32_t* p = (uint32_t*)(g_Wp + idx);
            p[h * 2]     = h2u(v[k16 * 16 + t4 * 2],     v[k16 * 16 + t4 * 2 + 1]);
            p[h * 2 + 1] = h2u(v[k16 * 16 + 8 + t4 * 2], v[k16 * 16 + 8 + t4 * 2 + 1]);
        }
    }
}

// =================================================================
// Kernel A: embedding gather + routing argmax + u = x @ W_in
// =================================================================
__global__ void embed_route_kernel(const int* __restrict__ idx,
                                   const float* __restrict__ W_emb,
                                   const float* __restrict__ G,
                                   const float* __restrict__ W_in) {
    __shared__ float xs[Dm];
    __shared__ float sred[NE][256];
    __shared__ float upart[256];

    const int tok = blockIdx.x;
    const int tid = threadIdx.x;
    const int id  = idx[tok];

    float sc[NE] = {0.f, 0.f, 0.f, 0.f};
    for (int d = tid; d < Dm; d += 256) {
        float v = W_emb[(size_t)id * Dm + d];
        xs[d] = v;
        g_x[tok * Dm + d] = v;
#pragma unroll
        for (int e = 0; e < NE; e++) sc[e] += v * G[e * Dm + d];
    }
#pragma unroll
    for (int e = 0; e < NE; e++) sred[e][tid] = sc[e];
    __syncthreads();
    for (int off = 128; off > 0; off >>= 1) {
        if (tid < off) {
#pragma unroll
            for (int e = 0; e < NE; e++) sred[e][tid] += sred[e][tid + off];
        }
        __syncthreads();
    }
    if (tid == 0) {
        int best = 0;
        float bv = sred[0][0];
#pragma unroll
        for (int e = 1; e < NE; e++)
            if (sred[e][0] > bv) { bv = sred[e][0]; best = e; }
        g_win[tok] = best;
    }

    const int j    = tid & 127;
    const int half = tid >> 7;
    const int e    = j >> 5;
    const int r    = j & 31;
    const float* w = W_in + (size_t)e * Dm * Rr + r;
    float acc = 0.f;
    const int d0 = half * (Dm / 2);
#pragma unroll 4
    for (int d = d0; d < d0 + Dm / 2; d++)
        acc += xs[d] * w[(size_t)d * Rr];
    upart[tid] = acc;
    __syncthreads();
    if (tid < 128) g_u[tok * (NE * Rr) + j] = upart[j] + upart[j + 128];
}

// =================================================================
// Kernel B: sequential recurrence (winner lists + u prefetch)
// =================================================================
__global__ void recur_kernel(const float* __restrict__ W_rec) {
    __shared__ int win_s[NTOK];
    __shared__ int lists[16][512];
    const int tid = threadIdx.x;
    for (int i = tid; i < NTOK; i += 512) win_s[i] = g_win[i];
    __syncthreads();

    const int w = tid >> 5, lane = tid & 31;
    const int e = w >> 2, b = w & 3;

    int n = 0;
    for (int base = 0; base < Tt; base += 32) {
        unsigned m = __ballot_sync(0xffffffffu, win_s[b * Tt + base + lane] == e);
        while (m) {
            int i = __ffs(m) - 1;
            m &= m - 1;
            lists[w][n++] = base + i;
        }
    }

    float wcol[Rr];
#pragma unroll
    for (int s = 0; s < Rr; s++) wcol[s] = W_rec[(e * Rr + s) * Rr + lane];

    float st = 0.f;
    float unext = 0.f;
    if (n > 0) unext = g_u[(b * Tt + lists[w][0]) * (NE * Rr) + e * Rr + lane];
    for (int i = 0; i < n; i++) {
        const float ucur = unext;
        if (i + 1 < n)
            unext = g_u[(b * Tt + lists[w][i + 1]) * (NE * Rr) + e * Rr + lane];
        float a0 = ucur, a1 = 0.f, a2 = 0.f, a3 = 0.f;
#pragma unroll
        for (int s = 0; s < Rr; s += 4) {
            a0 += __shfl_sync(0xffffffffu, st, s)     * wcol[s];
            a1 += __shfl_sync(0xffffffffu, st, s + 1) * wcol[s + 1];
            a2 += __shfl_sync(0xffffffffu, st, s + 2) * wcol[s + 2];
            a3 += __shfl_sync(0xffffffffu, st, s + 3) * wcol[s + 3];
        }
        st = tanhf((a0 + a1) + (a2 + a3));
        g_cand[(b * Tt + lists[w][i]) * Rr + lane] = st;
    }
}

// =================================================================
// Kernel C: y = cand @ W_out[winner] + x, LayerNorm, fp16-round,
//           write DIRECTLY into fragment-packed g_hp.
// m16n8k16 A frag: a0=(row g, k t4*2..+1) a1=(row g+8, same k)
//                  a2=(row g, k 8+t4*2..) a3=(row g+8, k 8+..)
// =================================================================
__global__ void out_ln_kernel(const float* __restrict__ W_out,
                              const float* __restrict__ gamma,
                              const float* __restrict__ beta) {
    __shared__ float cs[Rr];
    __shared__ float red[2][256];

    const int tok = blockIdx.x;
    const int tid = threadIdx.x;
    const int e   = g_win[tok];

    if (tid < Rr) cs[tid] = g_cand[tok * Rr + tid];
    __syncthreads();

    float y[3];
    float s = 0.f, sq = 0.f;
#pragma unroll
    for (int i = 0; i < 3; i++) {
        const int d = tid + i * 256;
        float acc = g_x[tok * Dm + d];
        const float* wo = W_out + (size_t)e * Rr * Dm + d;
#pragma unroll
        for (int r = 0; r < Rr; r++) acc += cs[r] * wo[(size_t)r * Dm];
        y[i] = acc;
        s += acc;
        sq += acc * acc;
    }
    red[0][tid] = s;
    red[1][tid] = sq;
    __syncthreads();
    for (int off = 128; off > 0; off >>= 1) {
        if (tid < off) {
            red[0][tid] += red[0][tid + off];
            red[1][tid] += red[1][tid + off];
        }
        __syncthreads();
    }
    const float mean = red[0][0] * (1.f / Dm);
    const float var  = red[1][0] * (1.f / Dm) - mean * mean;
    const float rstd = rsqrtf(var + 1e-5f);

    const int mblk    = tok >> 7;
    const int r       = tok & 127;
    const int m16     = r >> 4;
    const int g       = r & 7;
    const int rowhalf = (r >> 3) & 1;
#pragma unroll
    for (int i = 0; i < 3; i++) {
        const int d = tid + i * 256;
        const __half hv = __float2half_rn((y[i] - mean) * rstd * gamma[d] + beta[d]);
        const int c = d >> 6, kk = d & 63;
        const int k16 = kk >> 4, kin = kk & 15;
        const int khalf = kin >> 3, kp = kin & 7;
        const int t4 = kp >> 1, par = kp & 1;
        __half* base = (__half*)(g_hp +
            ((size_t)(mblk * NCHUNK + c) * 4 + k16) * 256 + m16 * 32 + g * 4 + t4);
        base[(khalf * 2 + rowhalf) * 2 + par] = hv;
    }
}

// =================================================================
// Kernel D: logits = h @ W_emb^T, mma.sync m16n8k16 fp16
// CTA 128x256, 8 warps (2 wm x 4 wn), warp tile 64x64.
// K chunks of 64 (4 k16 steps), 4-slot cp.async ring, frag ping-pong.
// =================================================================
constexpr int STAGE_BYTES = 49152;            // 16KB A + 32KB B
constexpr int SM_TOT      = 4 * STAGE_BYTES;  // 192KB

__global__ void __launch_bounds__(256, 1)
gemm_tc_kernel(float* __restrict__ out) {
    extern __shared__ char smem[];
    const uint32_t sbase = smem_u32(smem);
    const int tid  = threadIdx.x;
    const int warp = tid >> 5;
    const int lane = tid & 31;
    const int wm   = warp & 1;
    const int wn   = warp >> 1;
    const int g    = lane >> 2;
    const int t4   = lane & 3;
    const int mblk = blockIdx.x;
    const int nblk = blockIdx.y;

    const uint4* gA = g_hp + (size_t)mblk * NCHUNK * 1024;
    const uint4* gB = g_Wp + (size_t)nblk * NCHUNK * 2048;

    auto load_stage = [&](int slot, int c) {
        const uint32_t sA = sbase + slot * STAGE_BYTES;
        const uint32_t sB = sA + 16384;
        const uint4* a = gA + c * 1024;
        const uint4* b = gB + c * 2048;
#pragma unroll
        for (int t = 0; t < 4; t++) cp16(sA + (tid + t * 256) * 16, a + tid + t * 256);
#pragma unroll
        for (int t = 0; t < 8; t++) cp16(sB + (tid + t * 256) * 16, b + tid + t * 256);
        CP_COMMIT();
    };

    load_stage(0, 0);
    load_stage(1, 1);
    load_stage(2, 2);

    float acc[4][8][4];
#pragma unroll
    for (int mt = 0; mt < 4; mt++)
#pragma unroll
        for (int nt = 0; nt < 8; nt++)
#pragma unroll
            for (int k = 0; k < 4; k++) acc[mt][nt][k] = 0.f;

    // per-warp fragment base offsets within a stage
    const uint32_t aoff = (wm * 4) * 512 + lane * 16;            // + k16*4096 + mt*512
    const uint32_t boff = 16384 + wn * 2048 + lane * 16;         // + k16*8192 + pr*512

    uint32_t af[2][16], bf[2][16];

    auto lds_frags = [&](int p, uint32_t sS, int k16) {
#pragma unroll
        for (int mt = 0; mt < 4; mt++)
            LDS128(af[p][mt * 4], af[p][mt * 4 + 1], af[p][mt * 4 + 2], af[p][mt * 4 + 3],
                   sS + aoff + k16 * 4096 + mt * 512);
#pragma unroll
        for (int pr = 0; pr < 4; pr++)
            LDS128(bf[p][pr * 4], bf[p][pr * 4 + 1], bf[p][pr * 4 + 2], bf[p][pr * 4 + 3],
                   sS + boff + k16 * 8192 + pr * 512);
    };

    auto do_mma = [&](int p) {
#pragma unroll
        for (int mt = 0; mt < 4; mt++)
#pragma unroll
            for (int nt = 0; nt < 8; nt++) {
                const int bi = (nt >> 1) * 4 + (nt & 1) * 2;
                asm volatile(
                    "mma.sync.aligned.m16n8k16.row.col.f32.f16.f16.f32 "
                    "{%0,%1,%2,%3}, {%4,%5,%6,%7}, {%8,%9}, {%0,%1,%2,%3};\n"
                    : "+f"(acc[mt][nt][0]), "+f"(acc[mt][nt][1]),
                      "+f"(acc[mt][nt][2]), "+f"(acc[mt][nt][3])
                    : "r"(af[p][mt * 4]), "r"(af[p][mt * 4 + 1]),
                      "r"(af[p][mt * 4 + 2]), "r"(af[p][mt * 4 + 3]),
                      "r"(bf[p][bi]), "r"(bf[p][bi + 1]));
            }
    };

#pragma unroll 1
    for (int c = 0; c < NCHUNK; c++) {
        if (c < NCHUNK - 2)       { CP_WAIT(2); }
        else if (c == NCHUNK - 2) { CP_WAIT(1); }
        else                      { CP_WAIT(0); }
        __syncthreads();
        if (c + 3 < NCHUNK) load_stage((c + 3) & 3, c + 3);

        const uint32_t sS = sbase + (c & 3) * STAGE_BYTES;
        lds_frags(0, sS, 0);
#pragma unroll
        for (int k16 = 0; k16 < 4; k16++) {
            if (k16 < 3) lds_frags((k16 + 1) & 1, sS, k16 + 1);
            do_mma(k16 & 1);
        }
    }

    const int m0 = mblk * BM;
    const int n0 = nblk * BN;
#pragma unroll
    for (int mt = 0; mt < 4; mt++) {
        const int row0 = m0 + wm * 64 + mt * 16 + g;
#pragma unroll
        for (int nt = 0; nt < 8; nt++) {
            const int col = n0 + wn * 64 + nt * 8 + t4 * 2;
            if (col + 1 < NV) {
                out[(size_t)row0 * NV + col]           = acc[mt][nt][0];
                out[(size_t)row0 * NV + col + 1]       = acc[mt][nt][1];
                out[(size_t)(row0 + 8) * NV + col]     = acc[mt][nt][2];
                out[(size_t)(row0 + 8) * NV + col + 1] = acc[mt][nt][3];
            } else if (col < NV) {
                out[(size_t)row0 * NV + col]       = acc[mt][nt][0];
                out[(size_t)(row0 + 8) * NV + col] = acc[mt][nt][2];
            }
        }
    }
}

// =================================================================
// launch
// =================================================================
extern "C" void kernel_launch(void* const* d_in, const int* in_sizes, int n_in,
                              void* d_out, int out_size) {
    const int*   idx   = (const int*)d_in[0];
    const float* W_emb = (const float*)d_in[1];
    const float* G     = (const float*)d_in[2];
    const float* W_in  = (const float*)d_in[3];
    const float* W_rec = (const float*)d_in[4];
    const float* W_out = (const float*)d_in[5];
    const float* gamma = (const float*)d_in[6];
    const float* beta  = (const float*)d_in[7];
    float* out = (float*)d_out;

    cudaFuncSetAttribute(gemm_tc_kernel,
                         cudaFuncAttributeMaxDynamicSharedMemorySize, SM_TOT);

    perm_wemb_kernel<<<dim3(NCHUNK, NBLK), 256>>>(W_emb);
    embed_route_kernel<<<NTOK, 256>>>(idx, W_emb, G, W_in);
    recur_kernel<<<1, 512>>>(W_rec);
    out_ln_kernel<<<NTOK, 256>>>(W_out, gamma, beta);

    dim3 grid(MBLK, NBLK);
    gemm_tc_kernel<<<grid, 256, SM_TOT>>>(out);
}

// round 7
// speedup vs baseline: 1.9800x; 1.1554x over previous
#include <cuda_runtime.h>
#include <cuda_fp16.h>
#include <cstdint>
#include <cstring>

// ---------------- problem constants ----------------
constexpr int Dm    = 768;
constexpr int NE    = 4;
constexpr int Rr    = 32;
constexpr int Bb    = 4;
constexpr int Tt    = 512;
constexpr int NTOK  = Bb * Tt;   // 2048
constexpr int NV    = 50257;
constexpr int NVPAD = 50432;     // 394 * 128

constexpr int BM = 128, BN = 128;
constexpr int NCHUNK = Dm / 64;   // 12 chunks of K=64
constexpr int MBLK = NTOK / BM;   // 16
constexpr int NBLK = NVPAD / BN;  // 394

// ---------------- scratch ----------------
__device__ float  g_x[NTOK * Dm];
__device__ float  g_u[NTOK * NE * Rr];
__device__ float  g_cand[NTOK * Rr];
__device__ int    g_win[NTOK];
// A tiles, fp16 fragment-packed: per (mblk,c): [k16(4)][m16(8)][lane(32)] x uint4
__device__ uint4  g_hp[(size_t)MBLK * NCHUNK * 1024];
// B tiles, fp16 pair-packed: per (nblk,c): [k16(4)][wn(4)][pr(2)][lane(32)] x uint4
__device__ uint4  g_Wp[(size_t)NBLK * NCHUNK * 1024];

// ---------------- helpers ----------------
__device__ __forceinline__ uint32_t h2u(__half a, __half b) {
    __half2 t = __halves2half2(a, b);
    uint32_t u;
    memcpy(&u, &t, 4);
    return u;
}
__device__ __forceinline__ uint32_t smem_u32(const void* p) {
    uint32_t a;
    asm("{ .reg .u64 t; cvta.to.shared.u64 t, %1; cvt.u32.u64 %0, t; }" : "=r"(a) : "l"(p));
    return a;
}
__device__ __forceinline__ void cp16(uint32_t s, const void* g) {
    asm volatile("{ .reg .u64 gg; cvta.to.global.u64 gg, %1; cp.async.cg.shared.global [%0], [gg], 16; }"
                 :: "r"(s), "l"(g));
}
#define CP_COMMIT() asm volatile("cp.async.commit_group;" ::: "memory")
#define CP_WAIT(n)  asm volatile("cp.async.wait_group %0;" :: "n"(n) : "memory")
#define LDS128(r0, r1, r2, r3, a) \
    asm volatile("ld.shared.v4.b32 {%0,%1,%2,%3}, [%4];" \
                 : "=r"(r0), "=r"(r1), "=r"(r2), "=r"(r3) : "r"(a))

// =================================================================
// Kernel W: W_emb -> fp16, fragment-packed g_Wp   (BN=128 tiles)
// grid (NCHUNK, NBLK), 128 threads; thread = col (0..127) of the tile
// =================================================================
__global__ void perm_wemb_kernel(const float* __restrict__ W) {
    const int c    = blockIdx.x;
    const int nblk = blockIdx.y;
    const int col  = threadIdx.x;
    const int gcol = nblk * BN + col;

    __half v[64];
    if (gcol < NV) {
        const float4* src = (const float4*)(W + (size_t)gcol * Dm + c * 64);
#pragma unroll
        for (int i = 0; i < 16; i++) {
            float4 q = src[i];
            v[i * 4]     = __float2half_rn(q.x);
            v[i * 4 + 1] = __float2half_rn(q.y);
            v[i * 4 + 2] = __float2half_rn(q.z);
            v[i * 4 + 3] = __float2half_rn(q.w);
        }
    } else {
#pragma unroll
        for (int i = 0; i < 64; i++) v[i] = __float2half_rn(0.f);
    }
    const int wn = col >> 5, pr = (col >> 4) & 1, h = (col >> 3) & 1, g = col & 7;
#pragma unroll
    for (int k16 = 0; k16 < 4; k16++) {
#pragma unroll
        for (int t4 = 0; t4 < 4; t4++) {
            const size_t idx =
                ((((size_t)(nblk * NCHUNK + c) * 4 + k16) * 4 + wn) * 2 + pr) * 32 + g * 4 + t4;
            uint32_t* p = (uint32_t*)(g_Wp + idx);
            p[h * 2]     = h2u(v[k16 * 16 + t4 * 2],     v[k16 * 16 + t4 * 2 + 1]);
            p[h * 2 + 1] = h2u(v[k16 * 16 + 8 + t4 * 2], v[k16 * 16 + 8 + t4 * 2 + 1]);
        }
    }
}

// =================================================================
// Kernel A1: embedding gather + routing argmax (1 warp per token)
// =================================================================
__global__ void gather_route_kernel(const int* __restrict__ idx,
                                    const float* __restrict__ W_emb,
                                    const float* __restrict__ G) {
    const int tid  = threadIdx.x;
    const int warp = tid >> 5;
    const int lane = tid & 31;
    const int tok  = blockIdx.x * 8 + warp;
    const int id   = idx[tok];

    const float4* src = (const float4*)(W_emb + (size_t)id * Dm);
    const float4* g4  = (const float4*)G;
    float4* dst = (float4*)(g_x + (size_t)tok * Dm);

    float sc[NE] = {0.f, 0.f, 0.f, 0.f};
#pragma unroll
    for (int t = 0; t < 6; t++) {
        const int i = lane + t * 32;
        float4 v = src[i];
        dst[i] = v;
#pragma unroll
        for (int e = 0; e < NE; e++) {
            float4 gg = g4[e * (Dm / 4) + i];
            sc[e] += v.x * gg.x + v.y * gg.y + v.z * gg.z + v.w * gg.w;
        }
    }
#pragma unroll
    for (int off = 16; off > 0; off >>= 1)
#pragma unroll
        for (int e = 0; e < NE; e++)
            sc[e] += __shfl_down_sync(0xffffffffu, sc[e], off);
    if (lane == 0) {
        int best = 0;
        float bv = sc[0];
#pragma unroll
        for (int e = 1; e < NE; e++)
            if (sc[e] > bv) { bv = sc[e]; best = e; }
        g_win[tok] = best;
    }
}

// =================================================================
// Kernel A2: u = x @ W_in  (tiled SIMT GEMM, W_in staged in smem)
// grid 128 blocks (16 tokens each), 256 threads
// =================================================================
__global__ void uproj_kernel(const float* __restrict__ W_in) {
    __shared__ float xs[16][64];
    __shared__ float ws[64][128];

    const int tid  = threadIdx.x;
    const int tok0 = blockIdx.x * 16;
    const int tx   = tid & 31;   // out group: j0 = tx*4
    const int ty   = tid >> 5;   // token group: t0 = ty*2
    const int j0   = tx * 4;
    const int t0   = ty * 2;

    float acc[2][4] = {};

#pragma unroll 1
    for (int ch = 0; ch < 12; ch++) {
        const int d0 = ch * 64;
        // load x tile: 256 float4
        {
            const int row = tid >> 4, c4 = tid & 15;
            *(float4*)&xs[row][c4 * 4] =
                *(const float4*)(g_x + (size_t)(tok0 + row) * Dm + d0 + c4 * 4);
        }
        // load W_in tile: thread -> (d_loc, e), 8 float4 of 32 floats
        {
            const int d_loc = tid >> 2, e = tid & 3;
            const float4* srcw =
                (const float4*)(W_in + (size_t)e * Dm * Rr + (size_t)(d0 + d_loc) * Rr);
#pragma unroll
            for (int k = 0; k < 8; k++)
                *(float4*)&ws[d_loc][e * 32 + k * 4] = srcw[k];
        }
        __syncthreads();
#pragma unroll 8
        for (int d = 0; d < 64; d++) {
            const float4 w4 = *(const float4*)&ws[d][j0];
            const float x0 = xs[t0][d];
            const float x1 = xs[t0 + 1][d];
            acc[0][0] += x0 * w4.x; acc[0][1] += x0 * w4.y;
            acc[0][2] += x0 * w4.z; acc[0][3] += x0 * w4.w;
            acc[1][0] += x1 * w4.x; acc[1][1] += x1 * w4.y;
            acc[1][2] += x1 * w4.z; acc[1][3] += x1 * w4.w;
        }
        __syncthreads();
    }
#pragma unroll
    for (int tt = 0; tt < 2; tt++)
        *(float4*)&g_u[(size_t)(tok0 + t0 + tt) * (NE * Rr) + j0] =
            make_float4(acc[tt][0], acc[tt][1], acc[tt][2], acc[tt][3]);
}

// =================================================================
// Kernel B: sequential recurrence (winner lists + u prefetch)
// =================================================================
__global__ void recur_kernel(const float* __restrict__ W_rec) {
    __shared__ int win_s[NTOK];
    __shared__ int lists[16][512];
    const int tid = threadIdx.x;
    for (int i = tid; i < NTOK; i += 512) win_s[i] = g_win[i];
    __syncthreads();

    const int w = tid >> 5, lane = tid & 31;
    const int e = w >> 2, b = w & 3;

    int n = 0;
    for (int base = 0; base < Tt; base += 32) {
        unsigned m = __ballot_sync(0xffffffffu, win_s[b * Tt + base + lane] == e);
        while (m) {
            int i = __ffs(m) - 1;
            m &= m - 1;
            lists[w][n++] = base + i;
        }
    }

    float wcol[Rr];
#pragma unroll
    for (int s = 0; s < Rr; s++) wcol[s] = W_rec[(e * Rr + s) * Rr + lane];

    float st = 0.f;
    float unext = 0.f;
    if (n > 0) unext = g_u[(b * Tt + lists[w][0]) * (NE * Rr) + e * Rr + lane];
    for (int i = 0; i < n; i++) {
        const float ucur = unext;
        if (i + 1 < n)
            unext = g_u[(b * Tt + lists[w][i + 1]) * (NE * Rr) + e * Rr + lane];
        float a0 = ucur, a1 = 0.f, a2 = 0.f, a3 = 0.f;
#pragma unroll
        for (int s = 0; s < Rr; s += 4) {
            a0 += __shfl_sync(0xffffffffu, st, s)     * wcol[s];
            a1 += __shfl_sync(0xffffffffu, st, s + 1) * wcol[s + 1];
            a2 += __shfl_sync(0xffffffffu, st, s + 2) * wcol[s + 2];
            a3 += __shfl_sync(0xffffffffu, st, s + 3) * wcol[s + 3];
        }
        st = tanhf((a0 + a1) + (a2 + a3));
        g_cand[(b * Tt + lists[w][i]) * Rr + lane] = st;
    }
}

// =================================================================
// Kernel C: y = cand @ W_out[winner] + x, LayerNorm, fp16-round,
//           write DIRECTLY into fragment-packed g_hp.
// =================================================================
__global__ void out_ln_kernel(const float* __restrict__ W_out,
                              const float* __restrict__ gamma,
                              const float* __restrict__ beta) {
    __shared__ float cs[Rr];
    __shared__ float red[2][256];

    const int tok = blockIdx.x;
    const int tid = threadIdx.x;
    const int e   = g_win[tok];

    if (tid < Rr) cs[tid] = g_cand[tok * Rr + tid];
    __syncthreads();

    float y[3];
    float s = 0.f, sq = 0.f;
#pragma unroll
    for (int i = 0; i < 3; i++) {
        const int d = tid + i * 256;
        float acc = g_x[tok * Dm + d];
        const float* wo = W_out + (size_t)e * Rr * Dm + d;
#pragma unroll
        for (int r = 0; r < Rr; r++) acc += cs[r] * wo[(size_t)r * Dm];
        y[i] = acc;
        s += acc;
        sq += acc * acc;
    }
    red[0][tid] = s;
    red[1][tid] = sq;
    __syncthreads();
    for (int off = 128; off > 0; off >>= 1) {
        if (tid < off) {
            red[0][tid] += red[0][tid + off];
            red[1][tid] += red[1][tid + off];
        }
        __syncthreads();
    }
    const float mean = red[0][0] * (1.f / Dm);
    const float var  = red[1][0] * (1.f / Dm) - mean * mean;
    const float rstd = rsqrtf(var + 1e-5f);

    const int mblk    = tok >> 7;
    const int r       = tok & 127;
    const int m16     = r >> 4;
    const int g       = r & 7;
    const int rowhalf = (r >> 3) & 1;
#pragma unroll
    for (int i = 0; i < 3; i++) {
        const int d = tid + i * 256;
        const __half hv = __float2half_rn((y[i] - mean) * rstd * gamma[d] + beta[d]);
        const int c = d >> 6, kk = d & 63;
        const int k16 = kk >> 4, kin = kk & 15;
        const int khalf = kin >> 3, kp = kin & 7;
        const int t4 = kp >> 1, par = kp & 1;
        __half* base = (__half*)(g_hp +
            ((size_t)(mblk * NCHUNK + c) * 4 + k16) * 256 + m16 * 32 + g * 4 + t4);
        base[(khalf * 2 + rowhalf) * 2 + par] = hv;
    }
}

// =================================================================
// Kernel D: logits = h @ W_emb^T, mma.sync m16n8k16 fp16
// CTA 128x128, 8 warps (2 wm x 4 wn), warp tile 64x32.
// 3-stage ring (96KB) -> 2 CTAs/SM for latency hiding.
// =================================================================
constexpr int STAGE_BYTES = 32768;            // 16KB A + 16KB B
constexpr int SM_TOT      = 3 * STAGE_BYTES;  // 96KB

__global__ void __launch_bounds__(256, 2)
gemm_tc_kernel(float* __restrict__ out) {
    extern __shared__ char smem[];
    const uint32_t sbase = smem_u32(smem);
    const int tid  = threadIdx.x;
    const int warp = tid >> 5;
    const int lane = tid & 31;
    const int wm   = warp & 1;
    const int wn   = warp >> 1;   // 0..3
    const int g    = lane >> 2;
    const int t4   = lane & 3;
    const int mblk = blockIdx.x;
    const int nblk = blockIdx.y;

    const uint4* gA = g_hp + (size_t)mblk * NCHUNK * 1024;
    const uint4* gB = g_Wp + (size_t)nblk * NCHUNK * 1024;

    auto load_stage = [&](int slot, int c) {
        const uint32_t sS = sbase + slot * STAGE_BYTES;
        const uint4* a = gA + c * 1024;
        const uint4* b = gB + c * 1024;
#pragma unroll
        for (int t = 0; t < 4; t++) cp16(sS + (tid + t * 256) * 16, a + tid + t * 256);
#pragma unroll
        for (int t = 0; t < 4; t++) cp16(sS + 16384 + (tid + t * 256) * 16, b + tid + t * 256);
        CP_COMMIT();
    };

    load_stage(0, 0);
    load_stage(1, 1);

    float acc[4][4][4];
#pragma unroll
    for (int mt = 0; mt < 4; mt++)
#pragma unroll
        for (int nt = 0; nt < 4; nt++)
#pragma unroll
            for (int k = 0; k < 4; k++) acc[mt][nt][k] = 0.f;

    const uint32_t aoff = (wm * 4) * 512 + lane * 16;            // + k16*4096 + mt*512
    const uint32_t boff = 16384 + wn * 1024 + lane * 16;         // + k16*4096 + pr*512

#pragma unroll 1
    for (int c = 0; c < NCHUNK; c++) {
        if (c < NCHUNK - 1) { CP_WAIT(1); } else { CP_WAIT(0); }
        __syncthreads();
        if (c + 2 < NCHUNK) load_stage((c + 2) % 3, c + 2);

        const uint32_t sS = sbase + (c % 3) * STAGE_BYTES;
#pragma unroll
        for (int k16 = 0; k16 < 4; k16++) {
            uint32_t af[16], bf[8];
#pragma unroll
            for (int mt = 0; mt < 4; mt++)
                LDS128(af[mt * 4], af[mt * 4 + 1], af[mt * 4 + 2], af[mt * 4 + 3],
                       sS + aoff + k16 * 4096 + mt * 512);
#pragma unroll
            for (int pr = 0; pr < 2; pr++)
                LDS128(bf[pr * 4], bf[pr * 4 + 1], bf[pr * 4 + 2], bf[pr * 4 + 3],
                       sS + boff + k16 * 4096 + pr * 512);
#pragma unroll
            for (int mt = 0; mt < 4; mt++)
#pragma unroll
                for (int nt = 0; nt < 4; nt++) {
                    const int bi = (nt >> 1) * 4 + (nt & 1) * 2;
                    asm volatile(
                        "mma.sync.aligned.m16n8k16.row.col.f32.f16.f16.f32 "
                        "{%0,%1,%2,%3}, {%4,%5,%6,%7}, {%8,%9}, {%0,%1,%2,%3};\n"
                        : "+f"(acc[mt][nt][0]), "+f"(acc[mt][nt][1]),
                          "+f"(acc[mt][nt][2]), "+f"(acc[mt][nt][3])
                        : "r"(af[mt * 4]), "r"(af[mt * 4 + 1]),
                          "r"(af[mt * 4 + 2]), "r"(af[mt * 4 + 3]),
                          "r"(bf[bi]), "r"(bf[bi + 1]));
                }
        }
    }

    const int m0 = mblk * BM;
    const int n0 = nblk * BN;
#pragma unroll
    for (int mt = 0; mt < 4; mt++) {
        const int row0 = m0 + wm * 64 + mt * 16 + g;
#pragma unroll
        for (int nt = 0; nt < 4; nt++) {
            const int col = n0 + wn * 32 + nt * 8 + t4 * 2;
            if (col + 1 < NV) {
                out[(size_t)row0 * NV + col]           = acc[mt][nt][0];
                out[(size_t)row0 * NV + col + 1]       = acc[mt][nt][1];
                out[(size_t)(row0 + 8) * NV + col]     = acc[mt][nt][2];
                out[(size_t)(row0 + 8) * NV + col + 1] = acc[mt][nt][3];
            } else if (col < NV) {
                out[(size_t)row0 * NV + col]       = acc[mt][nt][0];
                out[(size_t)(row0 + 8) * NV + col] = acc[mt][nt][2];
            }
        }
    }
}

// =================================================================
// launch
// =================================================================
extern "C" void kernel_launch(void* const* d_in, const int* in_sizes, int n_in,
                              void* d_out, int out_size) {
    const int*   idx   = (const int*)d_in[0];
    const float* W_emb = (const float*)d_in[1];
    const float* G     = (const float*)d_in[2];
    const float* W_in  = (const float*)d_in[3];
    const float* W_rec = (const float*)d_in[4];
    const float* W_out = (const float*)d_in[5];
    const float* gamma = (const float*)d_in[6];
    const float* beta  = (const float*)d_in[7];
    float* out = (float*)d_out;

    cudaFuncSetAttribute(gemm_tc_kernel,
                         cudaFuncAttributeMaxDynamicSharedMemorySize, SM_TOT);

    perm_wemb_kernel<<<dim3(NCHUNK, NBLK), 128>>>(W_emb);
    gather_route_kernel<<<NTOK / 8, 256>>>(idx, W_emb, G);
    uproj_kernel<<<128, 256>>>(W_in);
    recur_kernel<<<1, 512>>>(W_rec);
    out_ln_kernel<<<NTOK, 256>>>(W_out, gamma, beta);

    dim3 grid(MBLK, NBLK);
    gemm_tc_kernel<<<grid, 256, SM_TOT>>>(out);
}